// round 4
// baseline (speedup 1.0000x reference)
#include <cuda_runtime.h>
#include <cstdint>

// Problem constants
#define BB   64      // batch
#define NN   4000    // nodes
#define CIN  64
#define COUT 64
#define DD   10      // embedding dim
#define KK   3       // Chebyshev order
#define NP   4096    // padded node dim
#define BC   4096    // B*CIN columns

// ---------------- scratch (static device globals; no allocation) ------------
__device__ float g_A [(size_t)NP * NP];   // adjacency (row-softmaxed), padded w/ zeros
__device__ float g_Xt[(size_t)NP * BC];   // X packed as [m][(b,c)], padded rows zero
__device__ float g_Y1[(size_t)NP * BC];   // A @ Xt
__device__ float g_Y2[(size_t)NP * BC];   // 2 A @ Y1 - Xt

// ---------------- kernel 1: adjacency build + row softmax -------------------
// one block per (padded) row n; logits = relu(emb[n] . emb[m]); softmax over m
__global__ __launch_bounds__(256) void build_adj(const float* __restrict__ emb) {
    const int n   = blockIdx.x;          // 0..4095
    const int tid = threadIdx.x;
    float* row = &g_A[(size_t)n * NP];
    __shared__ float red[256];

    if (n >= NN) {
        for (int m = tid; m < NP; m += 256) row[m] = 0.0f;
        return;
    }
    float e[DD];
#pragma unroll
    for (int d = 0; d < DD; ++d) e[d] = emb[n * DD + d];

    // pass 1: logits + local max (relu => all >= 0)
    float lmax = 0.0f;
    for (int m = tid; m < NN; m += 256) {
        const float* em = &emb[m * DD];
        float s = 0.0f;
#pragma unroll
        for (int d = 0; d < DD; ++d) s = fmaf(e[d], em[d], s);
        s = fmaxf(s, 0.0f);
        row[m] = s;
        lmax = fmaxf(lmax, s);
    }
    red[tid] = lmax; __syncthreads();
    for (int s = 128; s > 0; s >>= 1) {
        if (tid < s) red[tid] = fmaxf(red[tid], red[tid + s]);
        __syncthreads();
    }
    const float rmax = red[0];
    __syncthreads();

    // pass 2: exp + local sum (each thread owns same m's as pass 1)
    float lsum = 0.0f;
    for (int m = tid; m < NN; m += 256) {
        float v = __expf(row[m] - rmax);
        row[m] = v;
        lsum += v;
    }
    red[tid] = lsum; __syncthreads();
    for (int s = 128; s > 0; s >>= 1) {
        if (tid < s) red[tid] += red[tid + s];
        __syncthreads();
    }
    const float inv = 1.0f / red[0];

    // pass 3: normalize + zero pad columns
    for (int m = tid; m < NP; m += 256)
        row[m] = (m < NN) ? row[m] * inv : 0.0f;
}

// ---------------- kernel 2: pack X -> Xt[m][(b,c)] --------------------------
__global__ __launch_bounds__(256) void pack_x(const float* __restrict__ x) {
    const size_t idx = (size_t)blockIdx.x * 256 + threadIdx.x; // over NP*BC/4 float4s
    const int m  = (int)(idx >> 10);          // BC/4 = 1024 float4 per row
    const int j4 = (int)(idx & 1023);
    float4 v = make_float4(0.f, 0.f, 0.f, 0.f);
    if (m < NN) {
        const int b  = j4 >> 4;     // 16 float4 per (b,m)
        const int c4 = j4 & 15;
        v = reinterpret_cast<const float4*>(x)[((size_t)b * NN + m) * 16 + c4];
    }
    reinterpret_cast<float4*>(g_Xt)[(size_t)m * 1024 + j4] = v;
}

// ---------------- kernel 3: SGEMM  C = alpha*A@B + beta*Cin -----------------
// M=N=K=4096, 128x128 block tile, 16 k-tile, 8x8 per thread, 256 threads
__global__ __launch_bounds__(256) void sgemm4k(const float* __restrict__ A,
                                               const float* __restrict__ B,
                                               const float* __restrict__ Cin,
                                               float* __restrict__ C,
                                               float alpha, float beta) {
    __shared__ float As[16][128];   // transposed A tile
    __shared__ float Bs[16][128];

    const int tid = threadIdx.x;
    const int bm = blockIdx.y * 128;
    const int bn = blockIdx.x * 128;

    const int a_row  = tid >> 2;   // 0..63 (two iters cover 128 rows)
    const int a_col4 = tid & 3;    // float4 within 16 k-cols
    const int b_row  = tid >> 5;   // 0..7 (two iters cover 16 rows)
    const int b_col4 = tid & 31;   // float4 within 128 n-cols

    const int ty = tid >> 4;       // 0..15
    const int tx = tid & 15;       // 0..15

    float acc[8][8];
#pragma unroll
    for (int i = 0; i < 8; ++i)
#pragma unroll
        for (int j = 0; j < 8; ++j) acc[i][j] = 0.0f;

    const float4* A4 = reinterpret_cast<const float4*>(A);
    const float4* B4 = reinterpret_cast<const float4*>(B);

    for (int k0 = 0; k0 < NP; k0 += 16) {
#pragma unroll
        for (int r = 0; r < 2; ++r) {
            const int row = a_row + r * 64;
            float4 v = A4[(size_t)(bm + row) * 1024 + (k0 >> 2) + a_col4];
            As[a_col4 * 4 + 0][row] = v.x;
            As[a_col4 * 4 + 1][row] = v.y;
            As[a_col4 * 4 + 2][row] = v.z;
            As[a_col4 * 4 + 3][row] = v.w;
        }
#pragma unroll
        for (int r = 0; r < 2; ++r) {
            const int row = b_row + r * 8;
            float4 v = B4[(size_t)(k0 + row) * 1024 + (bn >> 2) + b_col4];
            *reinterpret_cast<float4*>(&Bs[row][b_col4 * 4]) = v;
        }
        __syncthreads();

#pragma unroll
        for (int kk = 0; kk < 16; ++kk) {
            float a_frag[8], b_frag[8];
            *reinterpret_cast<float4*>(&a_frag[0]) = *reinterpret_cast<float4*>(&As[kk][ty * 8]);
            *reinterpret_cast<float4*>(&a_frag[4]) = *reinterpret_cast<float4*>(&As[kk][ty * 8 + 4]);
            *reinterpret_cast<float4*>(&b_frag[0]) = *reinterpret_cast<float4*>(&Bs[kk][tx * 8]);
            *reinterpret_cast<float4*>(&b_frag[4]) = *reinterpret_cast<float4*>(&Bs[kk][tx * 8 + 4]);
#pragma unroll
            for (int i = 0; i < 8; ++i)
#pragma unroll
                for (int j = 0; j < 8; ++j)
                    acc[i][j] = fmaf(a_frag[i], b_frag[j], acc[i][j]);
        }
        __syncthreads();
    }

    // epilogue
#pragma unroll
    for (int i = 0; i < 8; ++i) {
        const size_t row = (size_t)(bm + ty * 8 + i);
#pragma unroll
        for (int j4 = 0; j4 < 2; ++j4) {
            const size_t col = (size_t)(bn + tx * 8 + j4 * 4);
            float4 r;
            r.x = alpha * acc[i][j4 * 4 + 0];
            r.y = alpha * acc[i][j4 * 4 + 1];
            r.z = alpha * acc[i][j4 * 4 + 2];
            r.w = alpha * acc[i][j4 * 4 + 3];
            if (beta != 0.0f) {
                float4 cv = reinterpret_cast<const float4*>(Cin)[(row * NP + col) >> 2];
                r.x = fmaf(beta, cv.x, r.x);
                r.y = fmaf(beta, cv.y, r.y);
                r.z = fmaf(beta, cv.z, r.z);
                r.w = fmaf(beta, cv.w, r.w);
            }
            reinterpret_cast<float4*>(C)[(row * NP + col) >> 2] = r;
        }
    }
}

// ---------------- kernel 4: per-node epilogue -------------------------------
// one block per node n. Builds W[n] (transposed, [o][ki], ki = k*64+i) and
// bias in SMEM, stages xg rows per batch, then 64x192x64 contraction.
#define SW_STRIDE 196   // 196 % 32 == 4 -> conflict-free float4 column reads

__global__ __launch_bounds__(256) void node_epilogue(const float* __restrict__ x,
                                                     const float* __restrict__ emb,
                                                     const float* __restrict__ wp,
                                                     const float* __restrict__ bp,
                                                     float* __restrict__ out) {
    extern __shared__ float smem[];
    float* sWt   = smem;                          // [64][SW_STRIDE]
    float* sXg   = sWt + 64 * SW_STRIDE;          // [64][192] as float4 [64][48]
    float* sBias = sXg + 64 * 192;                // [64]

    const int n   = blockIdx.x;
    const int tid = threadIdx.x;

    float e10[DD];
#pragma unroll
    for (int d = 0; d < DD; ++d) e10[d] = emb[n * DD + d];

    // W^T: sWt[o][ki] = sum_d e[d] * wp[d][ki][o], ki = k*64+i
    for (int eidx = tid; eidx < COUT * (KK * CIN); eidx += 256) {
        const int ki = eidx >> 6;
        const int o  = eidx & 63;
        float s = 0.0f;
#pragma unroll
        for (int d = 0; d < DD; ++d)
            s = fmaf(e10[d], wp[((size_t)d * (KK * CIN) + ki) * COUT + o], s);
        sWt[o * SW_STRIDE + ki] = s;
    }
    if (tid < COUT) {
        float s = 0.0f;
#pragma unroll
        for (int d = 0; d < DD; ++d) s = fmaf(e10[d], bp[d * COUT + tid], s);
        sBias[tid] = s;
    }

    // stage xg rows: [b][0:64]=x, [64:128]=Y1 row n, [128:192]=Y2 row n
    {
        const float4* x4  = reinterpret_cast<const float4*>(x);
        const float4* y1r = reinterpret_cast<const float4*>(g_Y1 + (size_t)n * BC);
        const float4* y2r = reinterpret_cast<const float4*>(g_Y2 + (size_t)n * BC);
        float4* sx4 = reinterpret_cast<float4*>(sXg);
        for (int j = tid; j < 1024; j += 256) {
            const int b  = j >> 4;
            const int c4 = j & 15;
            sx4[b * 48 + c4]      = x4[((size_t)b * NN + n) * 16 + c4];
            sx4[b * 48 + 16 + c4] = y1r[j];
            sx4[b * 48 + 32 + c4] = y2r[j];
        }
    }
    __syncthreads();

    // contraction: out[b][o] = sum_ki xg[b][ki] * Wt[o][ki] + bias[o]
    const int o    = tid & 63;
    const int bgrp = tid >> 6;   // 0..3; thread handles b = bgrp + 4*t
    float acc[16];
#pragma unroll
    for (int t = 0; t < 16; ++t) acc[t] = 0.0f;

    const float4* sx4 = reinterpret_cast<const float4*>(sXg);
    const float4* sw4 = reinterpret_cast<const float4*>(&sWt[o * SW_STRIDE]);
#pragma unroll
    for (int ib = 0; ib < 48; ++ib) {
        const float4 w = sw4[ib];
#pragma unroll
        for (int t = 0; t < 16; ++t) {
            const int b = bgrp + t * 4;
            const float4 xv = sx4[b * 48 + ib];
            acc[t] = fmaf(w.x, xv.x, acc[t]);
            acc[t] = fmaf(w.y, xv.y, acc[t]);
            acc[t] = fmaf(w.z, xv.z, acc[t]);
            acc[t] = fmaf(w.w, xv.w, acc[t]);
        }
    }

    const float bsv = sBias[o];
#pragma unroll
    for (int t = 0; t < 16; ++t) {
        const int b = bgrp + t * 4;
        out[((size_t)b * NN + n) * COUT + o] = acc[t] + bsv;
    }
}

// ---------------- launch ----------------------------------------------------
extern "C" void kernel_launch(void* const* d_in, const int* in_sizes, int n_in,
                              void* d_out, int out_size) {
    const float* x   = (const float*)d_in[0];   // [64,4000,64]
    const float* emb = (const float*)d_in[1];   // [4000,10]
    const float* wp  = (const float*)d_in[2];   // [10,3,64,64]
    const float* bp  = (const float*)d_in[3];   // [10,64]
    float* out = (float*)d_out;                 // [64,4000,64]

    float *A, *Xt, *Y1, *Y2;
    cudaGetSymbolAddress((void**)&A,  g_A);
    cudaGetSymbolAddress((void**)&Xt, g_Xt);
    cudaGetSymbolAddress((void**)&Y1, g_Y1);
    cudaGetSymbolAddress((void**)&Y2, g_Y2);

    // 1. adjacency + softmax (padded to 4096 rows)
    build_adj<<<NP, 256>>>(emb);

    // 2. pack X into [m][(b,c)]
    pack_x<<<(NP * (BC / 4)) / 256, 256>>>(x);

    // 3. Y1 = A @ Xt ; Y2 = 2 A @ Y1 - Xt
    dim3 gg(NP / 128, NP / 128);
    sgemm4k<<<gg, 256>>>(A, Xt, Xt, Y1, 1.0f, 0.0f);
    sgemm4k<<<gg, 256>>>(A, Y1, Xt, Y2, 2.0f, -1.0f);

    // 4. per-node weight generation + final contraction
    const int smem_bytes = (64 * SW_STRIDE + 64 * 192 + 64) * sizeof(float);
    cudaFuncSetAttribute(node_epilogue, cudaFuncAttributeMaxDynamicSharedMemorySize, smem_bytes);
    node_epilogue<<<NN, 256, smem_bytes>>>(x, emb, wp, bp, out);
}

// round 13
// speedup vs baseline: 2.3579x; 2.3579x over previous
#include <cuda_runtime.h>
#include <cuda_bf16.h>
#include <cstdint>

// Problem constants
#define BB   64
#define NN   4000
#define CIN  64
#define COUT 64
#define DD   10
#define KK   3
#define NP   4096
#define BC   4096

// ---------------- scratch (static device globals; no allocation) ------------
__device__ float g_A [(size_t)NP * NP];
__device__ float g_Y1[(size_t)NP * BC];
__device__ float g_Y2[(size_t)NP * BC];
__device__ __nv_bfloat16 g_Ah[(size_t)NP * NP];
__device__ __nv_bfloat16 g_Al[(size_t)NP * NP];
__device__ __nv_bfloat16 g_Bh[(size_t)NP * NP];
__device__ __nv_bfloat16 g_Bl[(size_t)NP * NP];

// ---------------- helpers ---------------------------------------------------
__device__ __forceinline__ uint32_t smem_u32(const void* p) {
    uint32_t a;
    asm("{ .reg .u64 t; cvta.to.shared.u64 t, %1; cvt.u32.u64 %0, t; }" : "=r"(a) : "l"(p));
    return a;
}

#define CP_ASYNC16(dst, src) \
    asm volatile("cp.async.cg.shared.global [%0], [%1], 16;" :: "r"(dst), "l"(src) : "memory")
#define CP_COMMIT() asm volatile("cp.async.commit_group;" ::: "memory")

__device__ __forceinline__ void ldsm_x4(uint32_t* d, uint32_t addr) {
    asm volatile("ldmatrix.sync.aligned.m8n8.x4.shared.b16 {%0,%1,%2,%3}, [%4];"
                 : "=r"(d[0]), "=r"(d[1]), "=r"(d[2]), "=r"(d[3]) : "r"(addr));
}

__device__ __forceinline__ void mma_bf16(float* c, const uint32_t* a, const uint32_t* b) {
    asm volatile("mma.sync.aligned.m16n8k16.row.col.f32.bf16.bf16.f32 "
                 "{%0,%1,%2,%3}, {%4,%5,%6,%7}, {%8,%9}, {%0,%1,%2,%3};"
                 : "+f"(c[0]), "+f"(c[1]), "+f"(c[2]), "+f"(c[3])
                 : "r"(a[0]), "r"(a[1]), "r"(a[2]), "r"(a[3]), "r"(b[0]), "r"(b[1]));
}

__device__ __forceinline__ void split2(float a, __nv_bfloat16& h, __nv_bfloat16& l) {
    h = __float2bfloat16(a);
    l = __float2bfloat16(a - __bfloat162float(h));
}

// ---------------- kernel 1: adjacency build + row softmax -------------------
__global__ __launch_bounds__(256) void build_adj(const float* __restrict__ emb) {
    const int n   = blockIdx.x;
    const int tid = threadIdx.x;
    float* row = &g_A[(size_t)n * NP];
    __shared__ float red[256];

    if (n >= NN) {
        for (int m = tid; m < NP; m += 256) row[m] = 0.0f;
        return;
    }
    float e[DD];
#pragma unroll
    for (int d = 0; d < DD; ++d) e[d] = emb[n * DD + d];

    float lmax = 0.0f;
    for (int m = tid; m < NN; m += 256) {
        const float* em = &emb[m * DD];
        float s = 0.0f;
#pragma unroll
        for (int d = 0; d < DD; ++d) s = fmaf(e[d], em[d], s);
        s = fmaxf(s, 0.0f);
        row[m] = s;
        lmax = fmaxf(lmax, s);
    }
    red[tid] = lmax; __syncthreads();
    for (int s = 128; s > 0; s >>= 1) {
        if (tid < s) red[tid] = fmaxf(red[tid], red[tid + s]);
        __syncthreads();
    }
    const float rmax = red[0];
    __syncthreads();

    float lsum = 0.0f;
    for (int m = tid; m < NN; m += 256) {
        float v = __expf(row[m] - rmax);
        row[m] = v;
        lsum += v;
    }
    red[tid] = lsum; __syncthreads();
    for (int s = 128; s > 0; s >>= 1) {
        if (tid < s) red[tid] += red[tid + s];
        __syncthreads();
    }
    const float inv = 1.0f / red[0];

    for (int m = tid; m < NP; m += 256)
        row[m] = (m < NN) ? row[m] * inv : 0.0f;
}

// ---------------- kernel 2: split A -> bf16 hi/lo ---------------------------
__global__ __launch_bounds__(256) void split_a_k() {
    const size_t i = (size_t)blockIdx.x * 256 + threadIdx.x;   // NP*NP/4 float4s
    float4 v = reinterpret_cast<const float4*>(g_A)[i];
    __nv_bfloat16 h0, l0, h1, l1, h2, l2, h3, l3;
    split2(v.x, h0, l0); split2(v.y, h1, l1);
    split2(v.z, h2, l2); split2(v.w, h3, l3);
    __nv_bfloat162* H = reinterpret_cast<__nv_bfloat162*>(g_Ah);
    __nv_bfloat162* L = reinterpret_cast<__nv_bfloat162*>(g_Al);
    H[2 * i]     = __halves2bfloat162(h0, h1);
    H[2 * i + 1] = __halves2bfloat162(h2, h3);
    L[2 * i]     = __halves2bfloat162(l0, l1);
    L[2 * i + 1] = __halves2bfloat162(l2, l3);
}

// ---------------- kernel 3: pack+transpose+split x -> B[(b,c)][m] -----------
__global__ __launch_bounds__(256) void pack_split_x(const float* __restrict__ x) {
    __shared__ float s[64][132];
    const int b  = blockIdx.y;
    const int m0 = blockIdx.x * 128;
    const int tid = threadIdx.x;
    const float4* x4 = reinterpret_cast<const float4*>(x);

#pragma unroll
    for (int it = 0; it < 8; ++it) {
        const int i  = it * 16 + (tid >> 4);
        const int c0 = (tid & 15) * 4;
        const int m  = m0 + i;
        float4 v = make_float4(0.f, 0.f, 0.f, 0.f);
        if (m < NN) v = x4[((size_t)b * NN + m) * 16 + (tid & 15)];
        s[c0 + 0][i] = v.x; s[c0 + 1][i] = v.y; s[c0 + 2][i] = v.z; s[c0 + 3][i] = v.w;
    }
    __syncthreads();

    __nv_bfloat162* BH = reinterpret_cast<__nv_bfloat162*>(g_Bh);
    __nv_bfloat162* BL = reinterpret_cast<__nv_bfloat162*>(g_Bl);
#pragma unroll
    for (int it = 0; it < 16; ++it) {
        const int c = it * 4 + (tid >> 6);
        const int j = tid & 63;
        __nv_bfloat16 h0, l0, h1, l1;
        split2(s[c][2 * j],     h0, l0);
        split2(s[c][2 * j + 1], h1, l1);
        const size_t off = (size_t)(b * 64 + c) * (NP / 2) + (m0 >> 1) + j;
        BH[off] = __halves2bfloat162(h0, h1);
        BL[off] = __halves2bfloat162(l0, l1);
    }
}

// ---------------- kernel 4: transpose+split Y1[k][n] -> B[n][k] -------------
__global__ __launch_bounds__(256) void split_y1_k() {
    __shared__ float t[32][33];
    const int k0 = blockIdx.x * 32;
    const int n0 = blockIdx.y * 32;
    const int tx = threadIdx.x;      // 0..31
    const int ty = threadIdx.y;      // 0..7
#pragma unroll
    for (int q = 0; q < 4; ++q)
        t[ty + 8 * q][tx] = g_Y1[(size_t)(k0 + ty + 8 * q) * BC + n0 + tx];
    __syncthreads();
#pragma unroll
    for (int q = 0; q < 4; ++q) {
        const float a = t[tx][ty + 8 * q];
        __nv_bfloat16 h, l; split2(a, h, l);
        const size_t off = (size_t)(n0 + ty + 8 * q) * NP + k0 + tx;
        g_Bh[off] = h;
        g_Bl[off] = l;
    }
}

// ---------------- kernel 5: mma.sync bf16x3 GEMM ----------------------------
// C[m][n] = alpha * sum_k (Ah+Al)[m][k]*(Bh+Bl)[n][k] + beta * Cin
// Operands K-major bf16. 128x128x32 tile, 8 warps (2x4), 3-stage cp.async.
#define TILE_BYTES  (128 * 64)          // one operand tile: 128 rows x 64B
#define STAGE_BYTES (4 * TILE_BYTES)    // Ah,Al,Bh,Bl = 32KB
#define GSTAGES     3
#define GEMM_SMEM   (GSTAGES * STAGE_BYTES)   // 96KB

// XOR swizzle: element (r, chunk c of 16B within 64B row)
__device__ __forceinline__ uint32_t sw_addr(uint32_t tileBase, int r, int c) {
    return tileBase + r * 64 + (((c ^ ((r >> 1) & 3))) << 4);
}

__global__ __launch_bounds__(256, 1) void gemm_mma(
    const __nv_bfloat16* __restrict__ Ah, const __nv_bfloat16* __restrict__ Al,
    const __nv_bfloat16* __restrict__ Bh, const __nv_bfloat16* __restrict__ Bl,
    const float* __restrict__ cin_x, float* __restrict__ C,
    float alpha, float beta, int cin_mode)
{
    extern __shared__ char smem[];
    const uint32_t sb = smem_u32(smem);
    const int tid  = threadIdx.x;
    const int wid  = tid >> 5;
    const int lane = tid & 31;
    const int bm = blockIdx.y * 128;
    const int bn = blockIdx.x * 128;
    const int wm = (wid >> 2) * 64;     // warp m offset (2 warps in m)
    const int wn = (wid & 3) * 32;      // warp n offset (4 warps in n)

    // chunk loader: 4 tiles x 128 rows x 64B, 2048 x 16B cp.async over 256 thr
    auto load_chunk = [&](int ck, int s) {
        const uint32_t stage = sb + s * STAGE_BYTES;
        const size_t kb = (size_t)ck * 64;    // byte offset along k
#pragma unroll
        for (int i = 0; i < 8; ++i) {
            const int idx = tid + i * 256;
            const int op = idx >> 9;          // 0..3
            const int r  = (idx >> 2) & 127;
            const int c  = idx & 3;
            const char* gb =
                (const char*)(op == 0 ? Ah : op == 1 ? Al : op == 2 ? Bh : Bl)
                + (size_t)((op < 2) ? bm : bn) * (NP * 2) + kb;
            CP_ASYNC16(sw_addr(stage + op * TILE_BYTES, r, c),
                       gb + (size_t)r * (NP * 2) + c * 16);
        }
        CP_COMMIT();
    };

    float acc[4][4][4];
#pragma unroll
    for (int mt = 0; mt < 4; ++mt)
#pragma unroll
        for (int nt = 0; nt < 4; ++nt)
#pragma unroll
            for (int q = 0; q < 4; ++q) acc[mt][nt][q] = 0.0f;

    load_chunk(0, 0);
    load_chunk(1, 1);

    for (int ck = 0; ck < 128; ++ck) {
        const int s = ck % 3;
        if (ck < 127) asm volatile("cp.async.wait_group 1;" ::: "memory");
        else          asm volatile("cp.async.wait_group 0;" ::: "memory");
        __syncthreads();

        const uint32_t stage = sb + s * STAGE_BYTES;
#pragma unroll
        for (int ks = 0; ks < 2; ++ks) {
            uint32_t ahf[4][4], alf[4][4], bhf[4][2], blf[4][2];
            // A fragments (m16k16 via ldmatrix.x4)
            const int arow = wm + (lane & 15);
            const int ac   = ks * 2 + (lane >> 4);
#pragma unroll
            for (int mt = 0; mt < 4; ++mt) {
                ldsm_x4(ahf[mt], sw_addr(stage + 0 * TILE_BYTES, arow + mt * 16, ac));
                ldsm_x4(alf[mt], sw_addr(stage + 1 * TILE_BYTES, arow + mt * 16, ac));
            }
            // B fragments: one ldmatrix.x4 covers two n8 tiles
            const int brow = wn + (lane & 7) + ((lane >> 4) << 3);
            const int bc   = ks * 2 + ((lane >> 3) & 1);
#pragma unroll
            for (int p = 0; p < 2; ++p) {
                uint32_t t[4];
                ldsm_x4(t, sw_addr(stage + 2 * TILE_BYTES, brow + p * 16, bc));
                bhf[2 * p][0] = t[0]; bhf[2 * p][1] = t[1];
                bhf[2 * p + 1][0] = t[2]; bhf[2 * p + 1][1] = t[3];
                ldsm_x4(t, sw_addr(stage + 3 * TILE_BYTES, brow + p * 16, bc));
                blf[2 * p][0] = t[0]; blf[2 * p][1] = t[1];
                blf[2 * p + 1][0] = t[2]; blf[2 * p + 1][1] = t[3];
            }
#pragma unroll
            for (int mt = 0; mt < 4; ++mt)
#pragma unroll
                for (int nt = 0; nt < 4; ++nt) {
                    mma_bf16(acc[mt][nt], ahf[mt], bhf[nt]);
                    mma_bf16(acc[mt][nt], ahf[mt], blf[nt]);
                    mma_bf16(acc[mt][nt], alf[mt], bhf[nt]);
                }
        }
        __syncthreads();
        if (ck + 2 < 128) load_chunk(ck + 2, (ck + 2) % 3);
    }

    // epilogue: C frag thread map: rows lane>>2 (+8), cols (lane&3)*2 (+1)
    const int r0 = lane >> 2;
    const int c0 = (lane & 3) * 2;
#pragma unroll
    for (int mt = 0; mt < 4; ++mt) {
#pragma unroll
        for (int nt = 0; nt < 4; ++nt) {
            const int n = bn + wn + nt * 8 + c0;
#pragma unroll
            for (int h = 0; h < 2; ++h) {
                const int m = bm + wm + mt * 16 + r0 + h * 8;
                float v0 = alpha * acc[mt][nt][h * 2 + 0];
                float v1 = alpha * acc[mt][nt][h * 2 + 1];
                if (cin_mode == 1 && m < NN) {
                    const float* cb = cin_x + ((size_t)(n >> 6) * NN + m) * 64 + (n & 63);
                    v0 = fmaf(beta, cb[0], v0);
                    v1 = fmaf(beta, cb[1], v1);
                }
                float2 o = make_float2(v0, v1);
                *reinterpret_cast<float2*>(C + (size_t)m * BC + n) = o;
            }
        }
    }
}

// ---------------- kernel 6: per-node epilogue -------------------------------
#define SW_STRIDE 196

__global__ __launch_bounds__(256) void node_epilogue(const float* __restrict__ x,
                                                     const float* __restrict__ emb,
                                                     const float* __restrict__ wp,
                                                     const float* __restrict__ bp,
                                                     float* __restrict__ out) {
    extern __shared__ float fsm[];
    float* sWt   = fsm;
    float* sXg   = sWt + 64 * SW_STRIDE;
    float* sBias = sXg + 64 * 192;

    const int n   = blockIdx.x;
    const int tid = threadIdx.x;

    float e10[DD];
#pragma unroll
    for (int d = 0; d < DD; ++d) e10[d] = emb[n * DD + d];

    for (int eidx = tid; eidx < COUT * (KK * CIN); eidx += 256) {
        const int ki = eidx >> 6;
        const int o  = eidx & 63;
        float s = 0.0f;
#pragma unroll
        for (int d = 0; d < DD; ++d)
            s = fmaf(e10[d], wp[((size_t)d * (KK * CIN) + ki) * COUT + o], s);
        sWt[o * SW_STRIDE + ki] = s;
    }
    if (tid < COUT) {
        float s = 0.0f;
#pragma unroll
        for (int d = 0; d < DD; ++d) s = fmaf(e10[d], bp[d * COUT + tid], s);
        sBias[tid] = s;
    }

    {
        const float4* x4  = reinterpret_cast<const float4*>(x);
        const float4* y1r = reinterpret_cast<const float4*>(g_Y1 + (size_t)n * BC);
        const float4* y2r = reinterpret_cast<const float4*>(g_Y2 + (size_t)n * BC);
        float4* sx4 = reinterpret_cast<float4*>(sXg);
        for (int j = tid; j < 1024; j += 256) {
            const int b  = j >> 4;
            const int c4 = j & 15;
            sx4[b * 48 + c4]      = x4[((size_t)b * NN + n) * 16 + c4];
            sx4[b * 48 + 16 + c4] = y1r[j];
            sx4[b * 48 + 32 + c4] = y2r[j];
        }
    }
    __syncthreads();

    const int o    = tid & 63;
    const int bgrp = tid >> 6;
    float acc[16];
#pragma unroll
    for (int t = 0; t < 16; ++t) acc[t] = 0.0f;

    const float4* sx4 = reinterpret_cast<const float4*>(sXg);
    const float4* sw4 = reinterpret_cast<const float4*>(&sWt[o * SW_STRIDE]);
#pragma unroll
    for (int ib = 0; ib < 48; ++ib) {
        const float4 w = sw4[ib];
#pragma unroll
        for (int t = 0; t < 16; ++t) {
            const int b = bgrp + t * 4;
            const float4 xv = sx4[b * 48 + ib];
            acc[t] = fmaf(w.x, xv.x, acc[t]);
            acc[t] = fmaf(w.y, xv.y, acc[t]);
            acc[t] = fmaf(w.z, xv.z, acc[t]);
            acc[t] = fmaf(w.w, xv.w, acc[t]);
        }
    }

    const float bsv = sBias[o];
#pragma unroll
    for (int t = 0; t < 16; ++t) {
        const int b = bgrp + t * 4;
        out[((size_t)b * NN + n) * COUT + o] = acc[t] + bsv;
    }
}

// ---------------- launch ----------------------------------------------------
extern "C" void kernel_launch(void* const* d_in, const int* in_sizes, int n_in,
                              void* d_out, int out_size) {
    const float* x   = (const float*)d_in[0];   // [64,4000,64]
    const float* emb = (const float*)d_in[1];   // [4000,10]
    const float* wp  = (const float*)d_in[2];   // [10,3,64,64]
    const float* bp  = (const float*)d_in[3];   // [10,64]
    float* out = (float*)d_out;

    float *Y1, *Y2;
    __nv_bfloat16 *Ah, *Al, *Bh, *Bl;
    cudaGetSymbolAddress((void**)&Y1, g_Y1);
    cudaGetSymbolAddress((void**)&Y2, g_Y2);
    cudaGetSymbolAddress((void**)&Ah, g_Ah);
    cudaGetSymbolAddress((void**)&Al, g_Al);
    cudaGetSymbolAddress((void**)&Bh, g_Bh);
    cudaGetSymbolAddress((void**)&Bl, g_Bl);

    // 1. adjacency + softmax
    build_adj<<<NP, 256>>>(emb);

    // 2. split A into bf16 hi/lo
    split_a_k<<<(NP * NP / 4) / 256, 256>>>();

    // 3. pack + transpose + split X -> B[(b,c)][m]
    pack_split_x<<<dim3(NP / 128, BB), 256>>>(x);

    // 4. Y1 = A @ X   (bf16x3 on HMMA tensor cores)
    cudaFuncSetAttribute(gemm_mma, cudaFuncAttributeMaxDynamicSharedMemorySize, GEMM_SMEM);
    dim3 gg(NP / 128, NP / 128);
    gemm_mma<<<gg, 256, GEMM_SMEM>>>(Ah, Al, Bh, Bl, nullptr, Y1, 1.0f, 0.0f, 0);

    // 5. transpose + split Y1 -> B[n][k]
    split_y1_k<<<dim3(NP / 32, NP / 32), dim3(32, 8)>>>();

    // 6. Y2 = 2 A @ Y1 - X
    gemm_mma<<<gg, 256, GEMM_SMEM>>>(Ah, Al, Bh, Bl, x, Y2, 2.0f, -1.0f, 1);

    // 7. per-node weight generation + final contraction
    const int smem_bytes = (64 * SW_STRIDE + 64 * 192 + 64) * sizeof(float);
    cudaFuncSetAttribute(node_epilogue, cudaFuncAttributeMaxDynamicSharedMemorySize, smem_bytes);
    node_epilogue<<<NN, 256, smem_bytes>>>(x, emb, wp, bp, out);
}

// round 15
// speedup vs baseline: 2.6612x; 1.1286x over previous
#include <cuda_runtime.h>
#include <cuda_bf16.h>
#include <cstdint>

// Problem constants
#define BB   64
#define NN   4000
#define CIN  64
#define COUT 64
#define DD   10
#define KK   3
#define NP   4096
#define BC   4096

// ---------------- scratch (static device globals; no allocation) ------------
__device__ float g_A [(size_t)NP * NP];
__device__ float g_Y1[(size_t)NP * BC];
__device__ float g_Y2[(size_t)NP * BC];
__device__ __nv_bfloat16 g_Ah[(size_t)NP * NP];
__device__ __nv_bfloat16 g_Al[(size_t)NP * NP];
__device__ __nv_bfloat16 g_Bh[(size_t)NP * NP];
__device__ __nv_bfloat16 g_Bl[(size_t)NP * NP];
__device__ __nv_bfloat16 g_Wh[(size_t)NN * (KK * CIN) * COUT];   // [n][o][ki]
__device__ __nv_bfloat16 g_Wl[(size_t)NN * (KK * CIN) * COUT];

// ---------------- helpers ---------------------------------------------------
__device__ __forceinline__ uint32_t smem_u32(const void* p) {
    uint32_t a;
    asm("{ .reg .u64 t; cvta.to.shared.u64 t, %1; cvt.u32.u64 %0, t; }" : "=r"(a) : "l"(p));
    return a;
}

#define CP_ASYNC16(dst, src) \
    asm volatile("cp.async.cg.shared.global [%0], [%1], 16;" :: "r"(dst), "l"(src) : "memory")
#define CP_COMMIT() asm volatile("cp.async.commit_group;" ::: "memory")

__device__ __forceinline__ void ldsm_x4(uint32_t* d, uint32_t addr) {
    asm volatile("ldmatrix.sync.aligned.m8n8.x4.shared.b16 {%0,%1,%2,%3}, [%4];"
                 : "=r"(d[0]), "=r"(d[1]), "=r"(d[2]), "=r"(d[3]) : "r"(addr));
}

__device__ __forceinline__ void mma_bf16(float* c, const uint32_t* a, const uint32_t* b) {
    asm volatile("mma.sync.aligned.m16n8k16.row.col.f32.bf16.bf16.f32 "
                 "{%0,%1,%2,%3}, {%4,%5,%6,%7}, {%8,%9}, {%0,%1,%2,%3};"
                 : "+f"(c[0]), "+f"(c[1]), "+f"(c[2]), "+f"(c[3])
                 : "r"(a[0]), "r"(a[1]), "r"(a[2]), "r"(a[3]), "r"(b[0]), "r"(b[1]));
}

__device__ __forceinline__ void split2(float a, __nv_bfloat16& h, __nv_bfloat16& l) {
    h = __float2bfloat16(a);
    l = __float2bfloat16(a - __bfloat162float(h));
}

// ---------------- kernel 1: adjacency build + row softmax -------------------
__global__ __launch_bounds__(256) void build_adj(const float* __restrict__ emb) {
    const int n   = blockIdx.x;
    const int tid = threadIdx.x;
    float* row = &g_A[(size_t)n * NP];
    __shared__ float red[256];

    if (n >= NN) {
        for (int m = tid; m < NP; m += 256) row[m] = 0.0f;
        return;
    }
    float e[DD];
#pragma unroll
    for (int d = 0; d < DD; ++d) e[d] = emb[n * DD + d];

    float lmax = 0.0f;
    for (int m = tid; m < NN; m += 256) {
        const float* em = &emb[m * DD];
        float s = 0.0f;
#pragma unroll
        for (int d = 0; d < DD; ++d) s = fmaf(e[d], em[d], s);
        s = fmaxf(s, 0.0f);
        row[m] = s;
        lmax = fmaxf(lmax, s);
    }
    red[tid] = lmax; __syncthreads();
    for (int s = 128; s > 0; s >>= 1) {
        if (tid < s) red[tid] = fmaxf(red[tid], red[tid + s]);
        __syncthreads();
    }
    const float rmax = red[0];
    __syncthreads();

    float lsum = 0.0f;
    for (int m = tid; m < NN; m += 256) {
        float v = __expf(row[m] - rmax);
        row[m] = v;
        lsum += v;
    }
    red[tid] = lsum; __syncthreads();
    for (int s = 128; s > 0; s >>= 1) {
        if (tid < s) red[tid] += red[tid + s];
        __syncthreads();
    }
    const float inv = 1.0f / red[0];

    for (int m = tid; m < NP; m += 256)
        row[m] = (m < NN) ? row[m] * inv : 0.0f;
}

// ---------------- kernel 2: split A -> bf16 hi/lo ---------------------------
__global__ __launch_bounds__(256) void split_a_k() {
    const size_t i = (size_t)blockIdx.x * 256 + threadIdx.x;   // NP*NP/4 float4s
    float4 v = reinterpret_cast<const float4*>(g_A)[i];
    __nv_bfloat16 h0, l0, h1, l1, h2, l2, h3, l3;
    split2(v.x, h0, l0); split2(v.y, h1, l1);
    split2(v.z, h2, l2); split2(v.w, h3, l3);
    __nv_bfloat162* H = reinterpret_cast<__nv_bfloat162*>(g_Ah);
    __nv_bfloat162* L = reinterpret_cast<__nv_bfloat162*>(g_Al);
    H[2 * i]     = __halves2bfloat162(h0, h1);
    H[2 * i + 1] = __halves2bfloat162(h2, h3);
    L[2 * i]     = __halves2bfloat162(l0, l1);
    L[2 * i + 1] = __halves2bfloat162(l2, l3);
}

// ---------------- kernel 3: pack+transpose+split x -> B[(b,c)][m] -----------
__global__ __launch_bounds__(256) void pack_split_x(const float* __restrict__ x) {
    __shared__ float s[64][132];
    const int b  = blockIdx.y;
    const int m0 = blockIdx.x * 128;
    const int tid = threadIdx.x;
    const float4* x4 = reinterpret_cast<const float4*>(x);

#pragma unroll
    for (int it = 0; it < 8; ++it) {
        const int i  = it * 16 + (tid >> 4);
        const int c0 = (tid & 15) * 4;
        const int m  = m0 + i;
        float4 v = make_float4(0.f, 0.f, 0.f, 0.f);
        if (m < NN) v = x4[((size_t)b * NN + m) * 16 + (tid & 15)];
        s[c0 + 0][i] = v.x; s[c0 + 1][i] = v.y; s[c0 + 2][i] = v.z; s[c0 + 3][i] = v.w;
    }
    __syncthreads();

    __nv_bfloat162* BH = reinterpret_cast<__nv_bfloat162*>(g_Bh);
    __nv_bfloat162* BL = reinterpret_cast<__nv_bfloat162*>(g_Bl);
#pragma unroll
    for (int it = 0; it < 16; ++it) {
        const int c = it * 4 + (tid >> 6);
        const int j = tid & 63;
        __nv_bfloat16 h0, l0, h1, l1;
        split2(s[c][2 * j],     h0, l0);
        split2(s[c][2 * j + 1], h1, l1);
        const size_t off = (size_t)(b * 64 + c) * (NP / 2) + (m0 >> 1) + j;
        BH[off] = __halves2bfloat162(h0, h1);
        BL[off] = __halves2bfloat162(l0, l1);
    }
}

// ---------------- kernel 4: transpose+split Y1[k][n] -> B[n][k] -------------
__global__ __launch_bounds__(256) void split_y1_k() {
    __shared__ float t[32][33];
    const int k0 = blockIdx.x * 32;
    const int n0 = blockIdx.y * 32;
    const int tx = threadIdx.x;      // 0..31
    const int ty = threadIdx.y;      // 0..7
#pragma unroll
    for (int q = 0; q < 4; ++q)
        t[ty + 8 * q][tx] = g_Y1[(size_t)(k0 + ty + 8 * q) * BC + n0 + tx];
    __syncthreads();
#pragma unroll
    for (int q = 0; q < 4; ++q) {
        const float a = t[tx][ty + 8 * q];
        __nv_bfloat16 h, l; split2(a, h, l);
        const size_t off = (size_t)(n0 + ty + 8 * q) * NP + k0 + tx;
        g_Bh[off] = h;
        g_Bl[off] = l;
    }
}

// ---------------- kernel 5: per-node weight pool W = emb @ wp ---------------
// W[n][ki][o] transposed to [n][o][ki], split hi/lo bf16.
// grid (8 ki-chunks of 24, 125 node tiles of 32), 256 threads.
__global__ __launch_bounds__(256) void gen_w(const float* __restrict__ emb,
                                             const float* __restrict__ wp) {
    extern __shared__ float gsm[];
    float* swp  = gsm;                 // [10][64 o][24 kk] = 15360 floats
    float* semb = gsm + 15360;         // [32][10]

    const int kc0 = blockIdx.x * 24;
    const int nt0 = blockIdx.y * 32;
    const int tid = threadIdx.x;

    // stage wp slice: swp[d*1536 + o*24 + kk] = wp[(d*192 + kc0+kk)*64 + o]
#pragma unroll
    for (int i = 0; i < 60; ++i) {
        const int f = tid + i * 256;           // 0..15359
        const int d = f / 1536;
        const int r = f - d * 1536;
        const int o  = r & 63;
        const int kk = r >> 6;
        swp[d * 1536 + o * 24 + kk] = wp[((size_t)d * 192 + kc0 + kk) * 64 + o];
    }
    if (tid < 256) { if (tid < 320 - 64) {} }
    if (tid < 256) semb[tid] = (tid < 320) ? emb[(size_t)nt0 * DD + tid] : 0.0f;
    if (tid < 64)  semb[256 + tid] = emb[(size_t)nt0 * DD + 256 + tid];
    __syncthreads();

    for (int nn = 0; nn < 32; ++nn) {
        const int n = nt0 + nn;
        float e[DD];
#pragma unroll
        for (int d = 0; d < DD; ++d) e[d] = semb[nn * DD + d];
#pragma unroll
        for (int i = 0; i < 6; ++i) {
            const int f  = tid + i * 256;      // 0..1535
            const int o  = f / 24;
            const int kk = f - o * 24;
            float s = 0.0f;
#pragma unroll
            for (int d = 0; d < DD; ++d)
                s = fmaf(e[d], swp[d * 1536 + o * 24 + kk], s);
            __nv_bfloat16 h, l; split2(s, h, l);
            const size_t off = (size_t)n * 12288 + (size_t)o * 192 + kc0 + kk;
            g_Wh[off] = h;
            g_Wl[off] = l;
        }
    }
}

// ---------------- kernel 6: mma.sync bf16x3 GEMM ----------------------------
// C[m][n] = alpha * sum_k (Ah+Al)[m][k]*(Bh+Bl)[n][k] + beta * Cin
// 128x128x32 tile, 8 warps (2x4), 4-stage cp.async, loads issued before MMA.
#define TILE_BYTES  (128 * 64)          // one operand tile: 128 rows x 64B
#define STAGE_BYTES (4 * TILE_BYTES)    // Ah,Al,Bh,Bl = 32KB
#define GSTAGES     4
#define GEMM_SMEM   (GSTAGES * STAGE_BYTES)   // 128KB

__device__ __forceinline__ uint32_t sw_addr(uint32_t tileBase, int r, int c) {
    return tileBase + r * 64 + (((c ^ ((r >> 1) & 3))) << 4);
}

__global__ __launch_bounds__(256, 1) void gemm_mma(
    const __nv_bfloat16* __restrict__ Ah, const __nv_bfloat16* __restrict__ Al,
    const __nv_bfloat16* __restrict__ Bh, const __nv_bfloat16* __restrict__ Bl,
    const float* __restrict__ cin_x, float* __restrict__ C,
    float alpha, float beta, int cin_mode)
{
    extern __shared__ char smem[];
    const uint32_t sb = smem_u32(smem);
    const int tid  = threadIdx.x;
    const int wid  = tid >> 5;
    const int lane = tid & 31;
    const int bm = blockIdx.y * 128;
    const int bn = blockIdx.x * 128;
    const int wm = (wid >> 2) * 64;
    const int wn = (wid & 3) * 32;

    auto load_chunk = [&](int ck, int s) {
        const uint32_t stage = sb + s * STAGE_BYTES;
        const size_t kb = (size_t)ck * 64;
#pragma unroll
        for (int i = 0; i < 8; ++i) {
            const int idx = tid + i * 256;
            const int op = idx >> 9;
            const int r  = (idx >> 2) & 127;
            const int c  = idx & 3;
            const char* gb =
                (const char*)(op == 0 ? Ah : op == 1 ? Al : op == 2 ? Bh : Bl)
                + (size_t)((op < 2) ? bm : bn) * (NP * 2) + kb;
            CP_ASYNC16(sw_addr(stage + op * TILE_BYTES, r, c),
                       gb + (size_t)r * (NP * 2) + c * 16);
        }
        CP_COMMIT();
    };

    float acc[4][4][4];
#pragma unroll
    for (int mt = 0; mt < 4; ++mt)
#pragma unroll
        for (int nt = 0; nt < 4; ++nt)
#pragma unroll
            for (int q = 0; q < 4; ++q) acc[mt][nt][q] = 0.0f;

    load_chunk(0, 0);
    load_chunk(1, 1);
    load_chunk(2, 2);

    for (int ck = 0; ck < 128; ++ck) {
        const int s = ck & 3;
        if (ck < 126)       asm volatile("cp.async.wait_group 2;" ::: "memory");
        else if (ck == 126) asm volatile("cp.async.wait_group 1;" ::: "memory");
        else                asm volatile("cp.async.wait_group 0;" ::: "memory");
        __syncthreads();

        if (ck + 3 < 128) load_chunk(ck + 3, (ck + 3) & 3);   // overlaps MMA below

        const uint32_t stage = sb + s * STAGE_BYTES;
#pragma unroll
        for (int ks = 0; ks < 2; ++ks) {
            uint32_t ahf[4][4], alf[4][4], bhf[4][2], blf[4][2];
            const int arow = wm + (lane & 15);
            const int ac   = ks * 2 + (lane >> 4);
#pragma unroll
            for (int mt = 0; mt < 4; ++mt) {
                ldsm_x4(ahf[mt], sw_addr(stage + 0 * TILE_BYTES, arow + mt * 16, ac));
                ldsm_x4(alf[mt], sw_addr(stage + 1 * TILE_BYTES, arow + mt * 16, ac));
            }
            const int brow = wn + (lane & 7) + ((lane >> 4) << 3);
            const int bc   = ks * 2 + ((lane >> 3) & 1);
#pragma unroll
            for (int p = 0; p < 2; ++p) {
                uint32_t t[4];
                ldsm_x4(t, sw_addr(stage + 2 * TILE_BYTES, brow + p * 16, bc));
                bhf[2 * p][0] = t[0]; bhf[2 * p][1] = t[1];
                bhf[2 * p + 1][0] = t[2]; bhf[2 * p + 1][1] = t[3];
                ldsm_x4(t, sw_addr(stage + 3 * TILE_BYTES, brow + p * 16, bc));
                blf[2 * p][0] = t[0]; blf[2 * p][1] = t[1];
                blf[2 * p + 1][0] = t[2]; blf[2 * p + 1][1] = t[3];
            }
#pragma unroll
            for (int mt = 0; mt < 4; ++mt)
#pragma unroll
                for (int nt = 0; nt < 4; ++nt) {
                    mma_bf16(acc[mt][nt], ahf[mt], bhf[nt]);
                    mma_bf16(acc[mt][nt], ahf[mt], blf[nt]);
                    mma_bf16(acc[mt][nt], alf[mt], bhf[nt]);
                }
        }
    }

    const int r0 = lane >> 2;
    const int c0 = (lane & 3) * 2;
#pragma unroll
    for (int mt = 0; mt < 4; ++mt) {
#pragma unroll
        for (int nt = 0; nt < 4; ++nt) {
            const int n = bn + wn + nt * 8 + c0;
#pragma unroll
            for (int h = 0; h < 2; ++h) {
                const int m = bm + wm + mt * 16 + r0 + h * 8;
                float v0 = alpha * acc[mt][nt][h * 2 + 0];
                float v1 = alpha * acc[mt][nt][h * 2 + 1];
                if (cin_mode == 1 && m < NN) {
                    const float* cb = cin_x + ((size_t)(n >> 6) * NN + m) * 64 + (n & 63);
                    v0 = fmaf(beta, cb[0], v0);
                    v1 = fmaf(beta, cb[1], v1);
                }
                float2 o = make_float2(v0, v1);
                *reinterpret_cast<float2*>(C + (size_t)m * BC + n) = o;
            }
        }
    }
}

// ---------------- kernel 7: per-node epilogue on tensor cores ---------------
// out[b][n][o] = sum_ki xg[b][ki] * W[n][o][ki] + bias[o]; bf16x3, M=64 N=64 K=192
#define EP_STRIDE 200                              // bf16 elems per row (400B)
#define EP_SMEM   (4 * 64 * EP_STRIDE * 2 + 256)   // Ah,Al,Wh,Wl + bias

__global__ __launch_bounds__(256, 2) void node_mma(const float* __restrict__ x,
                                                   const float* __restrict__ emb,
                                                   const float* __restrict__ bp,
                                                   float* __restrict__ out) {
    extern __shared__ char esm[];
    __nv_bfloat16* sA = reinterpret_cast<__nv_bfloat16*>(esm);  // Ah then Al
    float* sBias = reinterpret_cast<float*>(esm + 4 * 64 * EP_STRIDE * 2);
    const uint32_t sb    = smem_u32(esm);
    const uint32_t wbase = sb + 2u * 64 * EP_STRIDE * 2;        // Wh byte base

    const int n    = blockIdx.x;
    const int tid  = threadIdx.x;
    const int lane = tid & 31;
    const int wid  = tid >> 5;

    // 1. cp.async W hi/lo rows [o][192] -> padded smem rows (400B)
    {
        const char* gH = (const char*)(g_Wh + (size_t)n * 12288);
        const char* gL = (const char*)(g_Wl + (size_t)n * 12288);
#pragma unroll
        for (int i = 0; i < 6; ++i) {
            const int f = tid + i * 256;     // 0..1535
            const int o = f / 24, c = f - o * 24;
            CP_ASYNC16(wbase + o * 400 + c * 16, gH + o * 384 + c * 16);
            CP_ASYNC16(wbase + 64 * 400 + o * 400 + c * 16, gL + o * 384 + c * 16);
        }
        CP_COMMIT();
    }
    // 2. bias
    if (tid < 64) {
        float s = 0.0f;
#pragma unroll
        for (int d = 0; d < DD; ++d) s = fmaf(emb[n * DD + d], bp[d * 64 + tid], s);
        sBias[tid] = s;
    }
    // 3. stage + split xg rows: [b][0:64]=x, [64:128]=Y1, [128:192]=Y2
    {
        __nv_bfloat16* sAh = sA;
        __nv_bfloat16* sAl = sA + 64 * EP_STRIDE;
        auto put4 = [&](int b, int col, float4 v) {
            __nv_bfloat16 h0,l0,h1,l1,h2,l2,h3,l3;
            split2(v.x,h0,l0); split2(v.y,h1,l1); split2(v.z,h2,l2); split2(v.w,h3,l3);
            __nv_bfloat162* ph = reinterpret_cast<__nv_bfloat162*>(sAh + b * EP_STRIDE + col);
            __nv_bfloat162* pl = reinterpret_cast<__nv_bfloat162*>(sAl + b * EP_STRIDE + col);
            ph[0] = __halves2bfloat162(h0, h1); ph[1] = __halves2bfloat162(h2, h3);
            pl[0] = __halves2bfloat162(l0, l1); pl[1] = __halves2bfloat162(l2, l3);
        };
        const float4* x4  = reinterpret_cast<const float4*>(x);
        const float4* y1r = reinterpret_cast<const float4*>(g_Y1 + (size_t)n * BC);
        const float4* y2r = reinterpret_cast<const float4*>(g_Y2 + (size_t)n * BC);
#pragma unroll
        for (int i = 0; i < 4; ++i) {
            const int f = tid + i * 256;     // 0..1023
            const int b = f >> 4, i4 = f & 15;
            put4(b, i4 * 4,       x4[((size_t)b * NN + n) * 16 + i4]);
            put4(b, 64 + i4 * 4,  y1r[f]);
            put4(b, 128 + i4 * 4, y2r[f]);
        }
    }
    asm volatile("cp.async.wait_group 0;" ::: "memory");
    __syncthreads();

    // 4. mma: 8 warps = 4 m-tiles x 2 n-halves; warp = m16 x n32, K=192
    const int mt = wid >> 1;
    const int n0 = (wid & 1) * 32;
    float acc[4][4];
#pragma unroll
    for (int nt = 0; nt < 4; ++nt)
#pragma unroll
        for (int q = 0; q < 4; ++q) acc[nt][q] = 0.0f;

    const uint32_t aH = sb;
    const uint32_t aL = sb + 64u * EP_STRIDE * 2;
    const uint32_t wH = wbase;
    const uint32_t wL = wbase + 64u * 400;
#pragma unroll
    for (int ks = 0; ks < 12; ++ks) {
        uint32_t ahf[4], alf[4], bhf[4][2], blf[4][2];
        const int arow = mt * 16 + (lane & 15);
        const uint32_t acol = ks * 32 + (lane >> 4) * 16;
        ldsm_x4(ahf, aH + arow * 400 + acol);
        ldsm_x4(alf, aL + arow * 400 + acol);
        const int brow = (lane & 7) + ((lane >> 4) << 3);
        const uint32_t bcol = ks * 32 + ((lane >> 3) & 1) * 16;
#pragma unroll
        for (int p = 0; p < 2; ++p) {
            uint32_t t[4];
            ldsm_x4(t, wH + (n0 + p * 16 + brow) * 400 + bcol);
            bhf[2*p][0] = t[0]; bhf[2*p][1] = t[1];
            bhf[2*p+1][0] = t[2]; bhf[2*p+1][1] = t[3];
            ldsm_x4(t, wL + (n0 + p * 16 + brow) * 400 + bcol);
            blf[2*p][0] = t[0]; blf[2*p][1] = t[1];
            blf[2*p+1][0] = t[2]; blf[2*p+1][1] = t[3];
        }
#pragma unroll
        for (int nt = 0; nt < 4; ++nt) {
            mma_bf16(acc[nt], ahf, bhf[nt]);
            mma_bf16(acc[nt], ahf, blf[nt]);
            mma_bf16(acc[nt], alf, bhf[nt]);
        }
    }

    // 5. store with bias
    const int r0 = lane >> 2;
    const int c0 = (lane & 3) * 2;
#pragma unroll
    for (int nt = 0; nt < 4; ++nt) {
        const int o = n0 + nt * 8 + c0;
        const float b0 = sBias[o], b1 = sBias[o + 1];
#pragma unroll
        for (int h = 0; h < 2; ++h) {
            const int b = mt * 16 + r0 + h * 8;
            float2 v = make_float2(acc[nt][h * 2 + 0] + b0, acc[nt][h * 2 + 1] + b1);
            *reinterpret_cast<float2*>(out + ((size_t)b * NN + n) * 64 + o) = v;
        }
    }
}

// ---------------- launch ----------------------------------------------------
extern "C" void kernel_launch(void* const* d_in, const int* in_sizes, int n_in,
                              void* d_out, int out_size) {
    const float* x   = (const float*)d_in[0];   // [64,4000,64]
    const float* emb = (const float*)d_in[1];   // [4000,10]
    const float* wp  = (const float*)d_in[2];   // [10,3,64,64]
    const float* bp  = (const float*)d_in[3];   // [10,64]
    float* out = (float*)d_out;

    float *Y1, *Y2;
    __nv_bfloat16 *Ah, *Al, *Bh, *Bl;
    cudaGetSymbolAddress((void**)&Y1, g_Y1);
    cudaGetSymbolAddress((void**)&Y2, g_Y2);
    cudaGetSymbolAddress((void**)&Ah, g_Ah);
    cudaGetSymbolAddress((void**)&Al, g_Al);
    cudaGetSymbolAddress((void**)&Bh, g_Bh);
    cudaGetSymbolAddress((void**)&Bl, g_Bl);

    // 1. adjacency + softmax
    build_adj<<<NP, 256>>>(emb);

    // 2. split A into bf16 hi/lo
    split_a_k<<<(NP * NP / 4) / 256, 256>>>();

    // 3. pack + transpose + split X -> B[(b,c)][m]
    pack_split_x<<<dim3(NP / 128, BB), 256>>>(x);

    // 4. per-node weight pools (independent of GEMMs)
    const int gw_smem = (15360 + 320) * sizeof(float);
    cudaFuncSetAttribute(gen_w, cudaFuncAttributeMaxDynamicSharedMemorySize, gw_smem);
    gen_w<<<dim3(8, 125), 256, gw_smem>>>(emb, wp);

    // 5. Y1 = A @ X
    cudaFuncSetAttribute(gemm_mma, cudaFuncAttributeMaxDynamicSharedMemorySize, GEMM_SMEM);
    dim3 gg(NP / 128, NP / 128);
    gemm_mma<<<gg, 256, GEMM_SMEM>>>(Ah, Al, Bh, Bl, nullptr, Y1, 1.0f, 0.0f, 0);

    // 6. transpose + split Y1 -> B[n][k]
    split_y1_k<<<dim3(NP / 32, NP / 32), dim3(32, 8)>>>();

    // 7. Y2 = 2 A @ Y1 - X
    gemm_mma<<<gg, 256, GEMM_SMEM>>>(Ah, Al, Bh, Bl, x, Y2, 2.0f, -1.0f, 1);

    // 8. per-node contraction on tensor cores
    cudaFuncSetAttribute(node_mma, cudaFuncAttributeMaxDynamicSharedMemorySize, EP_SMEM);
    node_mma<<<NN, 256, EP_SMEM>>>(x, emb, bp, out);
}